// round 1
// baseline (speedup 1.0000x reference)
#include <cuda_runtime.h>
#include <cstdint>

// RandomStretchSqueeze: batched bilinear resample (half-pixel centers) to
// length L=floor(T*f), then center crop-or-pad back to T.
// B=512 rows, T=65536 (2^16) columns, fp32 in/out.

#define RS_B 512
#define RS_T 65536

// Per-row precomputed constants (allocation-free scratch).
__device__ int   g_rs_off[RS_B];
__device__ int   g_rs_L[RS_B];
__device__ float g_rs_scale[RS_B];

__global__ void rs_precompute_kernel(const float* __restrict__ f) {
    int b = blockIdx.x * blockDim.x + threadIdx.x;
    if (b >= RS_B) return;
    float fv = f[b];
    // 65536.0f * fv is EXACT in fp32 (power-of-two multiply); truncation toward
    // zero matches jnp astype(int32) on positive values bit-for-bit.
    int L = (int)(fv * (float)RS_T);
    if (L < 1) L = 1;
    int off = (L >= RS_T) ? ((L - RS_T) / 2) : (-((RS_T - L) / 2));
    g_rs_off[b]   = off;
    g_rs_L[b]     = L;
    // Correctly-rounded division (immune to --use_fast_math), matches jnp fp32 div.
    g_rs_scale[b] = __fdiv_rn((float)RS_T, (float)L);
}

__global__ void __launch_bounds__(256)
rs_resample_kernel(const float* __restrict__ in, float* __restrict__ out) {
    // Each thread produces 4 consecutive outputs (one float4 store).
    int tid = blockIdx.x * blockDim.x + threadIdx.x;
    int e   = tid << 2;              // first output element index
    int b   = e >> 16;               // row (T = 2^16)
    int j0  = e & (RS_T - 1);        // column of first element

    // Uniform within the warp (a warp never crosses a row boundary).
    int   off   = g_rs_off[b];
    int   L     = g_rs_L[b];
    float scale = g_rs_scale[b];

    const float* __restrict__ row = in + ((size_t)b << 16);

    float4 o;
    float* op = &o.x;
#pragma unroll
    for (int k = 0; k < 4; k++) {
        int r = j0 + k + off;        // index into the (virtual) resized signal
        float v = 0.0f;
        if (r >= 0 && r < L) {
            // half-pixel-center source coordinate
            float x = ((float)r + 0.5f) * scale - 0.5f;
            x = fminf(fmaxf(x, 0.0f), (float)(RS_T - 1));
            float x0f = floorf(x);
            float w   = x - x0f;
            int x0 = (int)x0f;
            int x1 = min(x0 + 1, RS_T - 1);
            float a0 = __ldg(row + x0);
            float a1 = __ldg(row + x1);
            // (1-w)*a0 + w*a1, written as a single fma (continuous across
            // floor boundaries, so ulp drift in x cannot blow up the error).
            v = fmaf(w, a1 - a0, a0);
        }
        op[k] = v;
    }
    *reinterpret_cast<float4*>(out + e) = o;
}

extern "C" void kernel_launch(void* const* d_in, const int* in_sizes, int n_in,
                              void* d_out, int out_size) {
    const float* inputs  = (const float*)d_in[0];   // [B, T] fp32
    const float* factors = (const float*)d_in[1];   // [B]    fp32
    float*       out     = (float*)d_out;           // [B, T] fp32

    rs_precompute_kernel<<<(RS_B + 127) / 128, 128>>>(factors);

    const int total_vec4 = (RS_B * RS_T) / 4;       // 8,388,608 threads
    rs_resample_kernel<<<total_vec4 / 256, 256>>>(inputs, out);
}

// round 3
// speedup vs baseline: 1.0320x; 1.0320x over previous
#include <cuda_runtime.h>
#include <cstdint>

// RandomStretchSqueeze: batched bilinear resample (half-pixel centers) to
// length L=floor(T*f), then center crop-or-pad back to T.
// B=512 rows, T=65536 (2^16) columns, fp32 in/out.
//
// Single fused kernel. Block = 256 threads, covers 1024 consecutive outputs
// of one row; thread's 4 elements are strided by blockDim so that warp lanes
// access CONSECUTIVE outputs -> gather addresses stride by scale (~1.0) ->
// each warp gather LDG touches 1-2 L1 lines (R1 layout touched ~15-18).

#define RS_B 512
#define RS_T 65536
#define SEG_SHIFT 10          // 1024 outputs per block
#define SEGS_PER_ROW 64       // 65536 / 1024

__global__ void __launch_bounds__(256)
rs_kernel(const float* __restrict__ in,
          const float* __restrict__ factors,
          float* __restrict__ out) {
    __shared__ int   s_off;
    __shared__ int   s_L;
    __shared__ float s_scale;

    const int b   = blockIdx.x >> 6;          // row
    const int seg = blockIdx.x & (SEGS_PER_ROW - 1);

    if (threadIdx.x == 0) {
        float fv = factors[b];
        // 65536.0f * fv is EXACT in fp32 (power-of-two multiply); truncation
        // toward zero matches jnp astype(int32) bit-for-bit (fv > 0).
        int L = (int)(fv * (float)RS_T);
        if (L < 1) L = 1;
        s_L     = L;
        s_off   = (L >= RS_T) ? ((L - RS_T) >> 1) : (-((RS_T - L) >> 1));
        // Correctly-rounded division regardless of fast-math flags.
        s_scale = __fdiv_rn((float)RS_T, (float)L);
    }
    __syncthreads();

    const int   off   = s_off;
    const int   L     = s_L;
    const float scale = s_scale;

    const float* __restrict__ row  = in  + ((size_t)b << 16);
    float*       __restrict__ orow = out + ((size_t)b << 16);

    const int j0 = (seg << SEG_SHIFT) + threadIdx.x;

#pragma unroll
    for (int k = 0; k < 4; k++) {
        const int j = j0 + (k << 8);          // k * blockDim.x
        const int r = j + off;                // index into virtual resized signal
        float v = 0.0f;
        if ((unsigned)r < (unsigned)L) {      // covers r<0 and r>=L (pad -> 0)
            // half-pixel-center source coordinate
            float x = ((float)r + 0.5f) * scale - 0.5f;
            x = fminf(fmaxf(x, 0.0f), (float)(RS_T - 1));
            float x0f = floorf(x);
            float w   = x - x0f;
            int x0 = (int)x0f;
            int x1 = min(x0 + 1, RS_T - 1);
            float a0 = __ldg(row + x0);
            float a1 = __ldg(row + x1);
            // (1-w)*a0 + w*a1 as one fma; continuous across floor boundaries,
            // so ulp drift in x cannot amplify error.
            v = fmaf(w, a1 - a0, a0);
        }
        orow[j] = v;
    }
}

extern "C" void kernel_launch(void* const* d_in, const int* in_sizes, int n_in,
                              void* d_out, int out_size) {
    const float* inputs  = (const float*)d_in[0];   // [B, T] fp32
    const float* factors = (const float*)d_in[1];   // [B]    fp32
    float*       out     = (float*)d_out;           // [B, T] fp32

    const int grid = RS_B * SEGS_PER_ROW;           // 32768 blocks
    rs_kernel<<<grid, 256>>>(inputs, factors, out);
}

// round 4
// speedup vs baseline: 1.0869x; 1.0531x over previous
#include <cuda_runtime.h>
#include <cstdint>

// RandomStretchSqueeze: batched bilinear resample (half-pixel centers) to
// length L=floor(T*f), then center crop-or-pad back to T.
// B=512 rows, T=65536 (2^16) columns, fp32 in/out.
//
// R4: smem-staged gather. Each block handles 2048 consecutive outputs of one
// row. The needed source window (<= 2048*1.1112+3 = 2279 floats) is staged
// into shared memory with coalesced float4 loads (pure streaming DRAM
// pattern), then the bilinear gather runs out of smem (LDS, conflict-free
// since lane-consecutive outputs give ~unit smem stride). This maximizes
// bytes-in-flight per L1tex miss-queue entry, which R1/R3 showed to be the
// binding resource (both pinned at 4.4 TB/s with wildly different L1 usage).

#define RS_B 512
#define RS_T 65536
#define SEG_OUT 2048            // outputs per block
#define SEGS_PER_ROW 32         // 65536 / 2048
#define WIN_FLOATS 2304         // >= 2281 worst-case window span, 16B multiple

__global__ void __launch_bounds__(256)
rs_kernel(const float* __restrict__ in,
          const float* __restrict__ factors,
          float* __restrict__ out) {
    __shared__ float s_win[WIN_FLOATS];

    const int b   = blockIdx.x >> 5;                 // row
    const int seg = blockIdx.x & (SEGS_PER_ROW - 1);
    const int j_start = seg * SEG_OUT;

    // ---- per-row constants (uniform; every thread computes identically) ----
    const float fv = __ldg(factors + b);
    // 65536.0f * fv is EXACT in fp32 (power-of-two multiply); truncation
    // toward zero matches jnp astype(int32) bit-for-bit (fv > 0).
    int L = (int)(fv * (float)RS_T);
    if (L < 1) L = 1;
    const int off = (L >= RS_T) ? ((L - RS_T) >> 1) : (-((RS_T - L) >> 1));
    // Correctly-rounded division regardless of fast-math flags.
    const float scale = __fdiv_rn((float)RS_T, (float)L);

    // ---- block source window [s0, s1) (uniform) ----
    int r_first = j_start + off;
    r_first = max(0, min(r_first, L - 1));
    int r_last = j_start + SEG_OUT - 1 + off;
    r_last = max(0, min(r_last, L - 1));

    float x_first = ((float)r_first + 0.5f) * scale - 0.5f;
    x_first = fminf(fmaxf(x_first, 0.0f), (float)(RS_T - 1));
    float x_last = ((float)r_last + 0.5f) * scale - 0.5f;
    x_last = fminf(fmaxf(x_last, 0.0f), (float)(RS_T - 1));

    const int s0 = ((int)x_first) & ~3;              // 16B-aligned start
    int s1 = (int)x_last + 2;                        // include x1 = floor+1
    if (s1 > RS_T) s1 = RS_T;
    const int nv4 = (s1 - s0 + 3) >> 2;              // float4 count (<= 576)

    // ---- stage window: coalesced float4 streaming loads ----
    const float4* __restrict__ src4 =
        reinterpret_cast<const float4*>(in + ((size_t)b << 16)) + (s0 >> 2);
    float4* __restrict__ dst4 = reinterpret_cast<float4*>(s_win);
#pragma unroll
    for (int i = 0; i < 3; i++) {
        const int idx = threadIdx.x + (i << 8);
        if (idx < nv4) dst4[idx] = __ldg(src4 + idx);
    }
    __syncthreads();

    // ---- bilinear gather from smem ----
    float* __restrict__ orow = out + ((size_t)b << 16);
    const int j0 = j_start + threadIdx.x;

#pragma unroll
    for (int k = 0; k < 8; k++) {
        const int j = j0 + (k << 8);                 // lane-consecutive outputs
        const int r = j + off;                       // virtual resized index
        float v = 0.0f;
        if ((unsigned)r < (unsigned)L) {             // pad region -> 0
            float x = ((float)r + 0.5f) * scale - 0.5f;
            x = fminf(fmaxf(x, 0.0f), (float)(RS_T - 1));
            const int   x0 = (int)x;                 // x >= 0 -> trunc == floor
            const float w  = x - (float)x0;
            const int   x1 = min(x0 + 1, RS_T - 1);
            const float a0 = s_win[x0 - s0];
            const float a1 = s_win[x1 - s0];
            // (1-w)*a0 + w*a1 as one fma; continuous across floor boundaries.
            v = fmaf(w, a1 - a0, a0);
        }
        orow[j] = v;
    }
}

extern "C" void kernel_launch(void* const* d_in, const int* in_sizes, int n_in,
                              void* d_out, int out_size) {
    const float* inputs  = (const float*)d_in[0];   // [B, T] fp32
    const float* factors = (const float*)d_in[1];   // [B]    fp32
    float*       out     = (float*)d_out;           // [B, T] fp32

    const int grid = RS_B * SEGS_PER_ROW;           // 16384 blocks
    rs_kernel<<<grid, 256>>>(inputs, factors, out);
}

// round 6
// speedup vs baseline: 1.1292x; 1.0390x over previous
#include <cuda_runtime.h>
#include <cstdint>

// RandomStretchSqueeze: batched bilinear resample (half-pixel centers) to
// length L=floor(T*f), then center crop-or-pad back to T.
// B=512 rows, T=65536 (2^16) cols, fp32.
//
// R5 (resubmit): smem-staged gather + block-uniform specialization.
//  - all-invalid blocks: store zeros, no staging.
//  - fast blocks (~95%): no bounds check, no clamps, no min, LDS pair with
//    immediate offset, stores off one base reg. ~11 issue slots/output.
//  - remaining edge blocks: R4 per-element path (clamps + min), unchanged.

#define RS_B 512
#define RS_T 65536
#define SEG_OUT 2048            // outputs per block
#define SEGS_PER_ROW 32         // 65536 / 2048
#define WIN_FLOATS 2304         // >= worst-case window span (2281), 16B mult

__global__ void __launch_bounds__(256)
rs_kernel(const float* __restrict__ in,
          const float* __restrict__ factors,
          float* __restrict__ out) {
    __shared__ float s_win[WIN_FLOATS];

    const int b   = blockIdx.x >> 5;                 // row
    const int seg = blockIdx.x & (SEGS_PER_ROW - 1);
    const int j_start = seg * SEG_OUT;

    // ---- per-row constants (uniform across block) ----
    const float fv = __ldg(factors + b);
    // 65536.0f * fv is EXACT (pow-2 multiply); trunc matches astype(int32).
    int L = (int)(fv * (float)RS_T);
    if (L < 1) L = 1;
    const int off = (L >= RS_T) ? ((L - RS_T) >> 1) : (-((RS_T - L) >> 1));
    const float scale = __fdiv_rn((float)RS_T, (float)L);   // correctly rounded

    float* __restrict__ orow = out + ((size_t)b << 16) + j_start;

    // ---- block classification (uniform) ----
    const int r_lo = j_start + off;                  // raw r of first output
    const int r_hi = r_lo + SEG_OUT - 1;             // raw r of last output

    if (r_hi < 0 || r_lo >= L) {                     // fully in pad region
#pragma unroll
        for (int k = 0; k < 8; k++)
            orow[threadIdx.x + (k << 8)] = 0.0f;
        return;
    }

    // ---- source window [s0, s1) (uniform) ----
    int rc_lo = max(0, min(r_lo, L - 1));
    int rc_hi = max(0, min(r_hi, L - 1));
    float x_lo = ((float)rc_lo + 0.5f) * scale - 0.5f;
    x_lo = fminf(fmaxf(x_lo, 0.0f), (float)(RS_T - 1));
    float x_hi = ((float)rc_hi + 0.5f) * scale - 0.5f;
    x_hi = fminf(fmaxf(x_hi, 0.0f), (float)(RS_T - 1));

    const int s0 = ((int)x_lo) & ~3;                 // 16B-aligned start
    int s1 = (int)x_hi + 2;                          // include x1 = floor+1
    if (s1 > RS_T) s1 = RS_T;
    const int nv4 = (s1 - s0 + 3) >> 2;              // <= 571 float4s

    // ---- stage window (coalesced, read-once streaming) ----
    const float4* __restrict__ src4 =
        reinterpret_cast<const float4*>(in + ((size_t)b << 16)) + (s0 >> 2);
    float4* __restrict__ dst4 = reinterpret_cast<float4*>(s_win);
#pragma unroll
    for (int i = 0; i < 3; i++) {
        const int idx = threadIdx.x + (i << 8);
        if (idx < nv4) dst4[idx] = __ldcs(src4 + idx);
    }
    __syncthreads();

    const float* __restrict__ wbase = s_win - s0;    // index by absolute x0
    float* __restrict__ obase = orow + threadIdx.x;

    // fast iff: every r valid, lower clamp can't fire (r>=1 -> x>0.86), upper
    // clamp can't fire and x0+1 is staged (x_hi < T-1 -> x1<=T-1, s1 unclamped)
    const bool fast = (r_lo >= 1) && (r_hi < L) && (x_hi < (float)(RS_T - 1));

    if (fast) {
        // rf == (float)r exactly (r < 2^24, +256.0f adds are exact), so the
        // x expression is bit-identical to the validated R4 arithmetic.
        float rf = (float)(r_lo + (int)threadIdx.x);
#pragma unroll
        for (int k = 0; k < 8; k++) {
            const float x  = (rf + 0.5f) * scale - 0.5f;
            const int   x0 = (int)x;                 // x > 0 -> trunc == floor
            const float w  = x - (float)x0;
            const float a0 = wbase[x0];              // LDS
            const float a1 = wbase[x0 + 1];          // LDS [same+4]
            obase[k << 8] = fmaf(w, a1 - a0, a0);    // STG [base + imm]
            rf += 256.0f;
        }
    } else {
        const int j0 = (int)threadIdx.x;
#pragma unroll
        for (int k = 0; k < 8; k++) {
            const int r = r_lo + j0 + (k << 8);
            float v = 0.0f;
            if ((unsigned)r < (unsigned)L) {
                float x = ((float)r + 0.5f) * scale - 0.5f;
                x = fminf(fmaxf(x, 0.0f), (float)(RS_T - 1));
                const int   x0 = (int)x;
                const float w  = x - (float)x0;
                const int   x1 = min(x0 + 1, RS_T - 1);  // x1 <= s1-1 staged
                const float a0 = wbase[x0];
                const float a1 = wbase[x1];
                v = fmaf(w, a1 - a0, a0);
            }
            obase[k << 8] = v;
        }
    }
}

extern "C" void kernel_launch(void* const* d_in, const int* in_sizes, int n_in,
                              void* d_out, int out_size) {
    const float* inputs  = (const float*)d_in[0];   // [B, T] fp32
    const float* factors = (const float*)d_in[1];   // [B]    fp32
    float*       out     = (float*)d_out;           // [B, T] fp32

    const int grid = RS_B * SEGS_PER_ROW;           // 16384 blocks
    rs_kernel<<<grid, 256>>>(inputs, factors, out);
}

// round 7
// speedup vs baseline: 1.1814x; 1.0462x over previous
#include <cuda_runtime.h>
#include <cstdint>

// RandomStretchSqueeze: batched bilinear resample (half-pixel centers) to
// length L=floor(T*f), then center crop-or-pad back to T. B=512, T=65536.
//
// R7: double-buffered cp.async pipeline. Block = 4 chunks x 2048 outputs.
// While chunk c is gathered from smem buffer (c&1), cp.async.cg streams
// chunk c+1 into the other buffer -> DRAM stays busy through gather phases
// (R6 showed DRAM idling at 57.6% because stage/gather phases serialized).

#define RS_B 512
#define RS_T 65536
#define CHUNK 2048
#define CHUNKS 4
#define OUT_PER_BLOCK (CHUNK * CHUNKS)      // 8192
#define BLOCKS_PER_ROW 8                    // 65536 / 8192
#define WIN_FLOATS 2304                     // >= worst-case span (2281), 16B mult

// Per-chunk source window [s0, s0+4*nv4). nv4=0 for pure-pad chunks.
__device__ __forceinline__ void rs_window(int j_start, int L, int off, float scale,
                                          int& s0, int& nv4) {
    const int r_lo = j_start + off;
    const int r_hi = r_lo + CHUNK - 1;
    if (r_hi < 0 || r_lo >= L) { s0 = 0; nv4 = 0; return; }
    const int rc_lo = max(0, min(r_lo, L - 1));
    const int rc_hi = max(0, min(r_hi, L - 1));
    float x_lo = ((float)rc_lo + 0.5f) * scale - 0.5f;
    x_lo = fminf(fmaxf(x_lo, 0.0f), (float)(RS_T - 1));
    float x_hi = ((float)rc_hi + 0.5f) * scale - 0.5f;
    x_hi = fminf(fmaxf(x_hi, 0.0f), (float)(RS_T - 1));
    s0 = ((int)x_lo) & ~3;                  // 16B-aligned start
    int s1 = (int)x_hi + 2;                 // include x1 = floor+1
    if (s1 > RS_T) s1 = RS_T;
    nv4 = (s1 - s0 + 3) >> 2;               // <= 571 float4s
}

__device__ __forceinline__ void rs_prefetch(const float* __restrict__ row,
                                            float* __restrict__ buf,
                                            int s0, int nv4, int tid) {
    const char* g = (const char*)(row + s0);
    unsigned sa = (unsigned)__cvta_generic_to_shared(buf);
#pragma unroll
    for (int i = 0; i < 3; i++) {
        const int idx = tid + (i << 8);
        if (idx < nv4) {
            asm volatile("cp.async.cg.shared.global [%0], [%1], 16;\n"
                         :: "r"(sa + idx * 16), "l"(g + (size_t)idx * 16)
                         : "memory");
        }
    }
    asm volatile("cp.async.commit_group;\n" ::: "memory");
}

__global__ void __launch_bounds__(256)
rs_kernel(const float* __restrict__ in,
          const float* __restrict__ factors,
          float* __restrict__ out) {
    __shared__ float s_win[2][WIN_FLOATS];

    const int b    = blockIdx.x >> 3;               // row
    const int part = blockIdx.x & (BLOCKS_PER_ROW - 1);
    const int tid  = threadIdx.x;

    // ---- per-row constants (uniform) ----
    const float fv = __ldg(factors + b);
    // 65536.0f * fv is EXACT (pow-2 multiply); trunc matches astype(int32).
    int L = (int)(fv * (float)RS_T);
    if (L < 1) L = 1;
    const int off = (L >= RS_T) ? ((L - RS_T) >> 1) : (-((RS_T - L) >> 1));
    const float scale = __fdiv_rn((float)RS_T, (float)L);   // correctly rounded

    const float* __restrict__ row = in + ((size_t)b << 16);
    const int j_block = part * OUT_PER_BLOCK;
    float* __restrict__ oblk = out + ((size_t)b << 16) + j_block;

    // ---- prologue: prefetch chunk 0 ----
    int s0_cur, nv4_cur;
    rs_window(j_block, L, off, scale, s0_cur, nv4_cur);
    rs_prefetch(row, s_win[0], s0_cur, nv4_cur, tid);

#pragma unroll 1
    for (int c = 0; c < CHUNKS; c++) {
        // issue prefetch for chunk c+1 into the other buffer
        int s0_nxt = 0, nv4_nxt = 0;
        if (c + 1 < CHUNKS) {
            rs_window(j_block + (c + 1) * CHUNK, L, off, scale, s0_nxt, nv4_nxt);
            rs_prefetch(row, s_win[(c + 1) & 1], s0_nxt, nv4_nxt, tid);
        } else {
            asm volatile("cp.async.commit_group;\n" ::: "memory");  // keep count
        }
        // wait: all groups but the newest are complete -> chunk c staged
        asm volatile("cp.async.wait_group 1;\n" ::: "memory");
        __syncthreads();

        // ---- gather chunk c ----
        const int   j_chunk = j_block + c * CHUNK;
        const int   r_lo    = j_chunk + off;
        const int   r_hi    = r_lo + CHUNK - 1;
        float* __restrict__ obase = oblk + c * CHUNK + tid;

        if (r_hi < 0 || r_lo >= L) {                // pure pad chunk
#pragma unroll
            for (int k = 0; k < 8; k++) obase[k << 8] = 0.0f;
        } else {
            const float* __restrict__ wbase = s_win[c & 1] - s0_cur;
            const int rc_hi = max(0, min(r_hi, L - 1));
            float x_hi = ((float)rc_hi + 0.5f) * scale - 0.5f;
            x_hi = fminf(fmaxf(x_hi, 0.0f), (float)(RS_T - 1));
            // fast iff: all r valid, clamps provably no-ops, x0+1 staged
            const bool fast = (r_lo >= 1) && (r_hi < L) &&
                              (x_hi < (float)(RS_T - 1));
            if (fast) {
                // rf == (float)r exactly (r < 2^24; +256.0f adds exact), so
                // x is bit-identical to the validated arithmetic.
                float rf = (float)(r_lo + tid);
#pragma unroll
                for (int k = 0; k < 8; k++) {
                    const float x  = (rf + 0.5f) * scale - 0.5f;
                    const int   x0 = (int)x;        // x > 0 -> trunc == floor
                    const float w  = x - (float)x0;
                    const float a0 = wbase[x0];
                    const float a1 = wbase[x0 + 1];
                    obase[k << 8] = fmaf(w, a1 - a0, a0);
                    rf += 256.0f;
                }
            } else {
#pragma unroll
                for (int k = 0; k < 8; k++) {
                    const int r = r_lo + tid + (k << 8);
                    float v = 0.0f;
                    if ((unsigned)r < (unsigned)L) {
                        float x = ((float)r + 0.5f) * scale - 0.5f;
                        x = fminf(fmaxf(x, 0.0f), (float)(RS_T - 1));
                        const int   x0 = (int)x;
                        const float w  = x - (float)x0;
                        const int   x1 = min(x0 + 1, RS_T - 1); // staged
                        v = fmaf(w, wbase[x1] - wbase[x0], wbase[x0]);
                    }
                    obase[k << 8] = v;
                }
            }
        }
        __syncthreads();       // gather done before next prefetch reuses buffer
        s0_cur  = s0_nxt;
        nv4_cur = nv4_nxt;
    }
}

extern "C" void kernel_launch(void* const* d_in, const int* in_sizes, int n_in,
                              void* d_out, int out_size) {
    const float* inputs  = (const float*)d_in[0];   // [B, T] fp32
    const float* factors = (const float*)d_in[1];   // [B]    fp32
    float*       out     = (float*)d_out;           // [B, T] fp32

    const int grid = RS_B * BLOCKS_PER_ROW;         // 4096 blocks
    rs_kernel<<<grid, 256>>>(inputs, factors, out);
}

// round 8
// speedup vs baseline: 1.1944x; 1.0110x over previous
#include <cuda_runtime.h>
#include <cstdint>

// RandomStretchSqueeze: batched bilinear resample (half-pixel centers) to
// length L=floor(T*f), then center crop-or-pad back to T. B=512, T=65536.
//
// R8: full-depth prefetch. Block = 4 chunks x 2048 outputs, each chunk with
// its OWN smem buffer (4 x 2304 floats = 36.9KB). All 4 cp.async groups are
// issued in the prologue (block's entire read demand in flight at once),
// then per chunk: wait_group (3-c) + one __syncthreads + gather. No buffer
// reuse -> no second sync, no stage/gather coupling (R7's wait_group-1
// double buffer left DRAM at 65.7%).

#define RS_B 512
#define RS_T 65536
#define CHUNK 2048
#define CHUNKS 4
#define OUT_PER_BLOCK (CHUNK * CHUNKS)      // 8192
#define BLOCKS_PER_ROW 8                    // 65536 / 8192
#define WIN_FLOATS 2304                     // >= worst-case span (2281), 16B mult

// Per-chunk source window [s0, s0+4*nv4). nv4=0 for pure-pad chunks.
__device__ __forceinline__ void rs_window(int j_start, int L, int off, float scale,
                                          int& s0, int& nv4) {
    const int r_lo = j_start + off;
    const int r_hi = r_lo + CHUNK - 1;
    if (r_hi < 0 || r_lo >= L) { s0 = 0; nv4 = 0; return; }
    const int rc_lo = max(0, min(r_lo, L - 1));
    const int rc_hi = max(0, min(r_hi, L - 1));
    float x_lo = ((float)rc_lo + 0.5f) * scale - 0.5f;
    x_lo = fminf(fmaxf(x_lo, 0.0f), (float)(RS_T - 1));
    float x_hi = ((float)rc_hi + 0.5f) * scale - 0.5f;
    x_hi = fminf(fmaxf(x_hi, 0.0f), (float)(RS_T - 1));
    s0 = ((int)x_lo) & ~3;                  // 16B-aligned start
    int s1 = (int)x_hi + 2;                 // include x1 = floor+1
    if (s1 > RS_T) s1 = RS_T;
    nv4 = (s1 - s0 + 3) >> 2;               // <= 571 float4s
}

__device__ __forceinline__ void rs_prefetch(const float* __restrict__ row,
                                            float* __restrict__ buf,
                                            int s0, int nv4, int tid) {
    const char* g = (const char*)(row + s0);
    unsigned sa = (unsigned)__cvta_generic_to_shared(buf);
#pragma unroll
    for (int i = 0; i < 3; i++) {
        const int idx = tid + (i << 8);
        if (idx < nv4) {
            asm volatile("cp.async.cg.shared.global [%0], [%1], 16;\n"
                         :: "r"(sa + idx * 16), "l"(g + (size_t)idx * 16)
                         : "memory");
        }
    }
    asm volatile("cp.async.commit_group;\n" ::: "memory");  // always (count!)
}

template <int N>
__device__ __forceinline__ void rs_wait() {
    asm volatile("cp.async.wait_group %0;\n" :: "n"(N) : "memory");
}

__global__ void __launch_bounds__(256)
rs_kernel(const float* __restrict__ in,
          const float* __restrict__ factors,
          float* __restrict__ out) {
    __shared__ float s_win[CHUNKS][WIN_FLOATS];   // 36.9 KB

    const int b    = blockIdx.x >> 3;               // row
    const int part = blockIdx.x & (BLOCKS_PER_ROW - 1);
    const int tid  = threadIdx.x;

    // ---- per-row constants (uniform) ----
    const float fv = __ldg(factors + b);
    // 65536.0f * fv is EXACT (pow-2 multiply); trunc matches astype(int32).
    int L = (int)(fv * (float)RS_T);
    if (L < 1) L = 1;
    const int off = (L >= RS_T) ? ((L - RS_T) >> 1) : (-((RS_T - L) >> 1));
    const float scale = __fdiv_rn((float)RS_T, (float)L);   // correctly rounded

    const float* __restrict__ row = in + ((size_t)b << 16);
    const int j_block = part * OUT_PER_BLOCK;
    float* __restrict__ oblk = out + ((size_t)b << 16) + j_block;

    // ---- prologue: compute all windows, issue ALL prefetch groups ----
    int s0a[CHUNKS];
#pragma unroll
    for (int c = 0; c < CHUNKS; c++) {
        int nv4;
        rs_window(j_block + c * CHUNK, L, off, scale, s0a[c], nv4);
        rs_prefetch(row, s_win[c], s0a[c], nv4, tid);    // group c
    }

    // ---- per-chunk: wait + gather (no buffer reuse, single sync) ----
#pragma unroll
    for (int c = 0; c < CHUNKS; c++) {
        if      (c == 0) rs_wait<3>();
        else if (c == 1) rs_wait<2>();
        else if (c == 2) rs_wait<1>();
        else             rs_wait<0>();
        __syncthreads();                  // make staged data CTA-visible

        const int   r_lo = j_block + c * CHUNK + off;
        const int   r_hi = r_lo + CHUNK - 1;
        float* __restrict__ obase = oblk + c * CHUNK + tid;

        if (r_hi < 0 || r_lo >= L) {                // pure pad chunk
#pragma unroll
            for (int k = 0; k < 8; k++) obase[k << 8] = 0.0f;
        } else {
            const float* __restrict__ wbase = s_win[c] - s0a[c];
            const int rc_hi = max(0, min(r_hi, L - 1));
            float x_hi = ((float)rc_hi + 0.5f) * scale - 0.5f;
            x_hi = fminf(fmaxf(x_hi, 0.0f), (float)(RS_T - 1));
            // fast iff: all r valid, clamps provably no-ops, x0+1 staged
            const bool fast = (r_lo >= 1) && (r_hi < L) &&
                              (x_hi < (float)(RS_T - 1));
            if (fast) {
                // rf == (float)r exactly (r < 2^24; +256.0f adds exact), so
                // x is bit-identical to the validated arithmetic.
                float rf = (float)(r_lo + tid);
#pragma unroll
                for (int k = 0; k < 8; k++) {
                    const float x  = (rf + 0.5f) * scale - 0.5f;
                    const int   x0 = (int)x;        // x > 0 -> trunc == floor
                    const float w  = x - (float)x0;
                    const float a0 = wbase[x0];
                    const float a1 = wbase[x0 + 1];
                    obase[k << 8] = fmaf(w, a1 - a0, a0);
                    rf += 256.0f;
                }
            } else {
#pragma unroll
                for (int k = 0; k < 8; k++) {
                    const int r = r_lo + tid + (k << 8);
                    float v = 0.0f;
                    if ((unsigned)r < (unsigned)L) {
                        float x = ((float)r + 0.5f) * scale - 0.5f;
                        x = fminf(fmaxf(x, 0.0f), (float)(RS_T - 1));
                        const int   x0 = (int)x;
                        const float w  = x - (float)x0;
                        const int   x1 = min(x0 + 1, RS_T - 1); // staged
                        v = fmaf(w, wbase[x1] - wbase[x0], wbase[x0]);
                    }
                    obase[k << 8] = v;
                }
            }
        }
        // no trailing sync: buffers are never reused
    }
}

extern "C" void kernel_launch(void* const* d_in, const int* in_sizes, int n_in,
                              void* d_out, int out_size) {
    const float* inputs  = (const float*)d_in[0];   // [B, T] fp32
    const float* factors = (const float*)d_in[1];   // [B]    fp32
    float*       out     = (float*)d_out;           // [B, T] fp32

    const int grid = RS_B * BLOCKS_PER_ROW;         // 4096 blocks
    rs_kernel<<<grid, 256>>>(inputs, factors, out);
}

// round 9
// speedup vs baseline: 1.2351x; 1.0341x over previous
#include <cuda_runtime.h>
#include <cstdint>

// RandomStretchSqueeze: batched bilinear resample (half-pixel centers) to
// length L=floor(T*f), then center crop-or-pad back to T. B=512, T=65536.
//
// R9: full-depth prefetch (R8) at restored occupancy. CHUNK 2048->1024:
// 4 private smem buffers of 1152 floats = 18.4KB/block, __launch_bounds__
// (256,8) pins 8 blocks/SM (R8's 36.9KB + 40 regs had dropped occ to 66%,
// which ate the MLP win). Same no-reuse, wait_group-countdown structure.

#define RS_B 512
#define RS_T 65536
#define CHUNK 1024
#define CHUNKS 4
#define OUT_PER_BLOCK (CHUNK * CHUNKS)      // 4096
#define BLOCKS_PER_ROW 16                   // 65536 / 4096
#define WIN_FLOATS 1152                     // >= worst span (~1143), 16B mult

// Per-chunk source window [s0, s0+4*nv4). nv4=0 for pure-pad chunks.
__device__ __forceinline__ void rs_window(int j_start, int L, int off, float scale,
                                          int& s0, int& nv4) {
    const int r_lo = j_start + off;
    const int r_hi = r_lo + CHUNK - 1;
    if (r_hi < 0 || r_lo >= L) { s0 = 0; nv4 = 0; return; }
    const int rc_lo = max(0, min(r_lo, L - 1));
    const int rc_hi = max(0, min(r_hi, L - 1));
    float x_lo = ((float)rc_lo + 0.5f) * scale - 0.5f;
    x_lo = fminf(fmaxf(x_lo, 0.0f), (float)(RS_T - 1));
    float x_hi = ((float)rc_hi + 0.5f) * scale - 0.5f;
    x_hi = fminf(fmaxf(x_hi, 0.0f), (float)(RS_T - 1));
    s0 = ((int)x_lo) & ~3;                  // 16B-aligned start
    int s1 = (int)x_hi + 2;                 // include x1 = floor+1
    if (s1 > RS_T) s1 = RS_T;
    nv4 = (s1 - s0 + 3) >> 2;               // <= 286 float4s
}

__device__ __forceinline__ void rs_prefetch(const float* __restrict__ row,
                                            float* __restrict__ buf,
                                            int s0, int nv4, int tid) {
    const char* g = (const char*)(row + s0);
    unsigned sa = (unsigned)__cvta_generic_to_shared(buf);
#pragma unroll
    for (int i = 0; i < 2; i++) {           // covers nv4 <= 512
        const int idx = tid + (i << 8);
        if (idx < nv4) {
            asm volatile("cp.async.cg.shared.global [%0], [%1], 16;\n"
                         :: "r"(sa + idx * 16), "l"(g + (size_t)idx * 16)
                         : "memory");
        }
    }
    asm volatile("cp.async.commit_group;\n" ::: "memory");  // always (count!)
}

template <int N>
__device__ __forceinline__ void rs_wait() {
    asm volatile("cp.async.wait_group %0;\n" :: "n"(N) : "memory");
}

__global__ void __launch_bounds__(256, 8)
rs_kernel(const float* __restrict__ in,
          const float* __restrict__ factors,
          float* __restrict__ out) {
    __shared__ float s_win[CHUNKS][WIN_FLOATS];   // 18.4 KB

    const int b    = blockIdx.x >> 4;               // row
    const int part = blockIdx.x & (BLOCKS_PER_ROW - 1);
    const int tid  = threadIdx.x;

    // ---- per-row constants (uniform) ----
    const float fv = __ldg(factors + b);
    // 65536.0f * fv is EXACT (pow-2 multiply); trunc matches astype(int32).
    int L = (int)(fv * (float)RS_T);
    if (L < 1) L = 1;
    const int off = (L >= RS_T) ? ((L - RS_T) >> 1) : (-((RS_T - L) >> 1));
    const float scale = __fdiv_rn((float)RS_T, (float)L);   // correctly rounded

    const float* __restrict__ row = in + ((size_t)b << 16);
    const int j_block = part * OUT_PER_BLOCK;
    float* __restrict__ oblk = out + ((size_t)b << 16) + j_block;

    // ---- prologue: compute all windows, issue ALL prefetch groups ----
    int s0a[CHUNKS];
#pragma unroll
    for (int c = 0; c < CHUNKS; c++) {
        int nv4;
        rs_window(j_block + c * CHUNK, L, off, scale, s0a[c], nv4);
        rs_prefetch(row, s_win[c], s0a[c], nv4, tid);    // group c
    }

    // ---- per-chunk: wait + gather (no buffer reuse, single sync) ----
#pragma unroll
    for (int c = 0; c < CHUNKS; c++) {
        if      (c == 0) rs_wait<3>();
        else if (c == 1) rs_wait<2>();
        else if (c == 2) rs_wait<1>();
        else             rs_wait<0>();
        __syncthreads();                  // make staged data CTA-visible

        const int   r_lo = j_block + c * CHUNK + off;
        const int   r_hi = r_lo + CHUNK - 1;
        float* __restrict__ obase = oblk + c * CHUNK + tid;

        if (r_hi < 0 || r_lo >= L) {                // pure pad chunk
#pragma unroll
            for (int k = 0; k < 4; k++) obase[k << 8] = 0.0f;
        } else {
            const float* __restrict__ wbase = s_win[c] - s0a[c];
            const int rc_hi = max(0, min(r_hi, L - 1));
            float x_hi = ((float)rc_hi + 0.5f) * scale - 0.5f;
            x_hi = fminf(fmaxf(x_hi, 0.0f), (float)(RS_T - 1));
            // fast iff: all r valid, clamps provably no-ops, x0+1 staged
            const bool fast = (r_lo >= 1) && (r_hi < L) &&
                              (x_hi < (float)(RS_T - 1));
            if (fast) {
                // rf == (float)r exactly (r < 2^24; +256.0f adds exact), so
                // x is bit-identical to the validated arithmetic.
                float rf = (float)(r_lo + tid);
#pragma unroll
                for (int k = 0; k < 4; k++) {
                    const float x  = (rf + 0.5f) * scale - 0.5f;
                    const int   x0 = (int)x;        // x > 0 -> trunc == floor
                    const float w  = x - (float)x0;
                    const float a0 = wbase[x0];
                    const float a1 = wbase[x0 + 1];
                    obase[k << 8] = fmaf(w, a1 - a0, a0);
                    rf += 256.0f;
                }
            } else {
#pragma unroll
                for (int k = 0; k < 4; k++) {
                    const int r = r_lo + tid + (k << 8);
                    float v = 0.0f;
                    if ((unsigned)r < (unsigned)L) {
                        float x = ((float)r + 0.5f) * scale - 0.5f;
                        x = fminf(fmaxf(x, 0.0f), (float)(RS_T - 1));
                        const int   x0 = (int)x;
                        const float w  = x - (float)x0;
                        const int   x1 = min(x0 + 1, RS_T - 1); // staged
                        v = fmaf(w, wbase[x1] - wbase[x0], wbase[x0]);
                    }
                    obase[k << 8] = v;
                }
            }
        }
        // no trailing sync: buffers are never reused
    }
}

extern "C" void kernel_launch(void* const* d_in, const int* in_sizes, int n_in,
                              void* d_out, int out_size) {
    const float* inputs  = (const float*)d_in[0];   // [B, T] fp32
    const float* factors = (const float*)d_in[1];   // [B]    fp32
    float*       out     = (float*)d_out;           // [B, T] fp32

    const int grid = RS_B * BLOCKS_PER_ROW;         // 8192 blocks
    rs_kernel<<<grid, 256>>>(inputs, factors, out);
}